// round 12
// baseline (speedup 1.0000x reference)
#include <cuda_runtime.h>
#include <cuda_bf16.h>
#include <cuda_fp16.h>
#include <cstdint>
#include <math.h>

#define D_MODEL 384
#define N_HEADS 8
#define HEAD_DIM 48
#define BATCH 2
#define NTOK 2048
#define TOTAL_TOK (BATCH * NTOK)
#define QKV_COLS (3 * D_MODEL)

// Scratch (allocation-free)
__device__ __half   g_xh[TOTAL_TOK * D_MODEL];
__device__ __half   g_xl[TOTAL_TOK * D_MODEL];
__device__ uint32_t g_wqt[QKV_COLS * (D_MODEL / 2)];   // [n][kp] half2
__device__ uint32_t g_wot[D_MODEL * (D_MODEL / 2)];
__device__ __half   g_qkvh[TOTAL_TOK * QKV_COLS];
__device__ __half   g_oh[TOTAL_TOK * D_MODEL];
__device__ __half   g_ol[TOTAL_TOK * D_MODEL];

// ---------------------------------------------------------------------------
// helpers
// ---------------------------------------------------------------------------
__device__ __forceinline__ void mma_f16(float* d, const uint32_t* a, const uint32_t* b) {
    asm volatile(
        "mma.sync.aligned.m16n8k16.row.col.f32.f16.f16.f32 "
        "{%0,%1,%2,%3}, {%4,%5,%6,%7}, {%8,%9}, {%0,%1,%2,%3};"
        : "+f"(d[0]), "+f"(d[1]), "+f"(d[2]), "+f"(d[3])
        : "r"(a[0]), "r"(a[1]), "r"(a[2]), "r"(a[3]), "r"(b[0]), "r"(b[1]));
}

__device__ __forceinline__ uint32_t pack_f16(float x, float y) {
    uint32_t r; asm("cvt.rn.f16x2.f32 %0, %1, %2;" : "=r"(r) : "f"(y), "f"(x)); return r;
}
__device__ __forceinline__ void split_pair_f16(float v0, float v1, uint32_t& hi, uint32_t& lo) {
    hi = pack_f16(v0, v1);
    __half2 h2 = *reinterpret_cast<__half2*>(&hi);
    float2 back = __half22float2(h2);
    lo = pack_f16(v0 - back.x, v1 - back.y);
}

__device__ __forceinline__ float sqrt_approx(float x) {
    float r; asm("sqrt.approx.f32 %0, %1;" : "=f"(r) : "f"(x)); return r;
}
__device__ __forceinline__ uint32_t ex2_h2(uint32_t x) {
    uint32_t r; asm("ex2.approx.f16x2 %0, %1;" : "=r"(r) : "r"(x)); return r;
}

// ---------------------------------------------------------------------------
// conversion kernels (run once per launch; all graph-capturable)
// ---------------------------------------------------------------------------
__global__ __launch_bounds__(256)
void split_x_kernel(const float* __restrict__ x, __half* __restrict__ xh,
                    __half* __restrict__ xl, int n2)
{
    int i = blockIdx.x * 256 + threadIdx.x;
    if (i >= n2) return;
    float2 v = *reinterpret_cast<const float2*>(x + 2 * (size_t)i);
    uint32_t hi, lo;
    split_pair_f16(v.x, v.y, hi, lo);
    *reinterpret_cast<uint32_t*>(xh + 2 * (size_t)i) = hi;
    *reinterpret_cast<uint32_t*>(xl + 2 * (size_t)i) = lo;
}

// W[K][N] row-major -> Wt[n][kp] with half2 = (W[2kp][n], W[2kp+1][n])
__global__ __launch_bounds__(256)
void wtrans_kernel(const float* __restrict__ W, uint32_t* __restrict__ Wt, int N, int K)
{
    int idx = blockIdx.x * 256 + threadIdx.x;
    if (idx >= N * (K / 2)) return;
    int n = idx % N;
    int kp = idx / N;
    float b0 = __ldg(W + (size_t)(2 * kp) * N + n);
    float b1 = __ldg(W + (size_t)(2 * kp + 1) * N + n);
    Wt[(size_t)n * (K / 2) + kp] = pack_f16(b0, b1);
}

// ---------------------------------------------------------------------------
// 2-term FP16 GEMM, pre-converted operands (no cvt in hot loop):
//   C = (Ah + Al) @ B + bias ; A as split halves, B as transposed-paired half2.
// BM=128, BN=64, BK=32; 256 threads; warp tile 32x32.
// ---------------------------------------------------------------------------
#define GBM 128
#define GBN 64
#define GBK 32
#define ASTR 20
#define BSTR 20

template <typename OutT>
__global__ __launch_bounds__(256)
void gemm_h_kernel(const __half* __restrict__ Ah, const __half* __restrict__ Al,
                   const uint32_t* __restrict__ Bt, const float* __restrict__ bias,
                   OutT* __restrict__ C, int M, int N, int K)
{
    __shared__ uint32_t sAh[GBM * ASTR];
    __shared__ uint32_t sAl[GBM * ASTR];
    __shared__ uint32_t sBh[GBN * BSTR];

    const int tid = threadIdx.x;
    const int w = tid >> 5;
    const int lane = tid & 31;
    const int g = lane >> 2;
    const int t = lane & 3;
    const int wm = w >> 1;
    const int wn = w & 1;
    const int row0 = blockIdx.y * GBM;
    const int col0 = blockIdx.x * GBN;
    const int Kp = K / 2;

    float acc[2][4][4];
    #pragma unroll
    for (int mt = 0; mt < 2; mt++)
        #pragma unroll
        for (int nb = 0; nb < 4; nb++)
            #pragma unroll
            for (int e = 0; e < 4; e++) acc[mt][nb][e] = 0.f;

    for (int k0 = 0; k0 < K; k0 += GBK) {
        __syncthreads();
        // A: 128 rows x 32 halves; 4 threads/row, one uint4 (8 halves) each
        #pragma unroll
        for (int ii = 0; ii < 2; ii++) {
            const int i = tid + 256 * ii;
            const int r = i >> 2, q = i & 3;
            uint4 vh = *reinterpret_cast<const uint4*>(Ah + (size_t)(row0 + r) * K + k0 + 8 * q);
            uint4 vl = *reinterpret_cast<const uint4*>(Al + (size_t)(row0 + r) * K + k0 + 8 * q);
            *reinterpret_cast<uint4*>(&sAh[r * ASTR + 4 * q]) = vh;
            *reinterpret_cast<uint4*>(&sAl[r * ASTR + 4 * q]) = vl;
        }
        // B: 64 cols x 16 kp; 4 threads/col, one uint4 (4 kp) each
        {
            const int n = tid >> 2, q = tid & 3;
            uint4 vb = *reinterpret_cast<const uint4*>(Bt + (size_t)(col0 + n) * Kp + (k0 >> 1) + 4 * q);
            *reinterpret_cast<uint4*>(&sBh[n * BSTR + 4 * q]) = vb;
        }
        __syncthreads();

        #pragma unroll
        for (int kc = 0; kc < 2; kc++) {
            uint32_t ah[2][4], al[2][4];
            #pragma unroll
            for (int mt = 0; mt < 2; mt++) {
                const int rA = (32 * wm + 16 * mt + g) * ASTR + 8 * kc;
                const int rB = rA + 8 * ASTR;
                ah[mt][0] = sAh[rA + t];     al[mt][0] = sAl[rA + t];
                ah[mt][1] = sAh[rB + t];     al[mt][1] = sAl[rB + t];
                ah[mt][2] = sAh[rA + t + 4]; al[mt][2] = sAl[rA + t + 4];
                ah[mt][3] = sAh[rB + t + 4]; al[mt][3] = sAl[rB + t + 4];
            }
            #pragma unroll
            for (int nb = 0; nb < 4; nb++) {
                const int nbase = (32 * wn + 8 * nb + g) * BSTR + 8 * kc;
                uint32_t bh_[2];
                bh_[0] = sBh[nbase + t];
                bh_[1] = sBh[nbase + t + 4];
                mma_f16(acc[0][nb], ah[0], bh_);
                mma_f16(acc[1][nb], ah[1], bh_);
                mma_f16(acc[0][nb], al[0], bh_);
                mma_f16(acc[1][nb], al[1], bh_);
            }
        }
    }

    #pragma unroll
    for (int mt = 0; mt < 2; mt++) {
        const int rA = row0 + 32 * wm + 16 * mt + g;
        #pragma unroll
        for (int nb = 0; nb < 4; nb++) {
            const int c = col0 + 32 * wn + 8 * nb + 2 * t;
            const float bx = bias[c], by = bias[c + 1];
            if constexpr (sizeof(OutT) == 4) {
                *reinterpret_cast<float2*>((float*)C + (size_t)rA * N + c) =
                    make_float2(acc[mt][nb][0] + bx, acc[mt][nb][1] + by);
                *reinterpret_cast<float2*>((float*)C + (size_t)(rA + 8) * N + c) =
                    make_float2(acc[mt][nb][2] + bx, acc[mt][nb][3] + by);
            } else {
                *reinterpret_cast<uint32_t*>((__half*)C + (size_t)rA * N + c) =
                    pack_f16(acc[mt][nb][0] + bx, acc[mt][nb][1] + by);
                *reinterpret_cast<uint32_t*>((__half*)C + (size_t)(rA + 8) * N + c) =
                    pack_f16(acc[mt][nb][2] + bx, acc[mt][nb][3] + by);
            }
        }
    }
}

// ---------------------------------------------------------------------------
// Fused attention (fp16 qkv input, half2 softmax, ex2.f16x2 -> direct frags)
// ---------------------------------------------------------------------------
#define TJ 64
#define MQ 256
#define N_ITERS (NTOK / TJ)
#define KSTR 28
#define VSTR 36
#define LOG2E 1.4426950408889634f

__global__ __launch_bounds__(256, 1)
void attn_mma_kernel(const __half* __restrict__ qkv, const float* __restrict__ coords,
                     const float* __restrict__ W_dist,
                     __half* __restrict__ oh, __half* __restrict__ ol)
{
    __shared__ uint32_t sKh[TJ * KSTR];
    __shared__ uint32_t sVh[HEAD_DIM * VSTR];
    __shared__ __half2 sC2[3][TJ / 2];

    const int tid = threadIdx.x;
    const int w = tid >> 5;
    const int lane = tid & 31;
    const int g = lane >> 2;
    const int t = lane & 3;
    const int bh = blockIdx.y;
    const int b = bh >> 3, h = bh & 7;
    const int q0 = blockIdx.x * MQ;

    const float qscale = 0.14433756729740643f * LOG2E;
    const float wd2 = __ldg(W_dist + h) * LOG2E;
    const __half2 qs2 = __float2half2_rn(qscale);

    const __half* gKh = qkv + (size_t)(b * NTOK) * QKV_COLS + D_MODEL + h * HEAD_DIM;
    const __half* gVh = gKh + D_MODEL;

    uint32_t pK[6];
    uint32_t pV[6];
    float pCa = 0.f, pCb = 0.f;
    const int ccomp = tid % 3;      // valid for tid<96
    const int ckp = tid / 3;

    // ---- initial prefetch (tile 0) ----
    #pragma unroll
    for (int ii = 0; ii < 6; ii++) {
        const int i = tid + 256 * ii;
        const int r = i / 24, cu = i % 24;
        pK[ii] = *reinterpret_cast<const uint32_t*>(gKh + (size_t)r * QKV_COLS + 2 * cu);
    }
    #pragma unroll
    for (int ii = 0; ii < 3; ii++) {
        const int p = tid + 256 * ii;
        const int kp = p / 24, dp = p % 24;
        pV[2 * ii]     = *reinterpret_cast<const uint32_t*>(gVh + (size_t)(2 * kp) * QKV_COLS + 2 * dp);
        pV[2 * ii + 1] = *reinterpret_cast<const uint32_t*>(gVh + (size_t)(2 * kp + 1) * QKV_COLS + 2 * dp);
    }
    if (tid < 96) {
        pCa = __ldg(coords + (size_t)(b * NTOK + 2 * ckp) * 3 + ccomp);
        pCb = __ldg(coords + (size_t)(b * NTOK + 2 * ckp + 1) * 3 + ccomp);
    }

    // ---- Q fragments: direct u32 loads from fp16 qkv, scaled in h2 ----
    uint32_t qh[2][3][4];
    {
        const __half* gQ = qkv + (size_t)(b * NTOK + q0) * QKV_COLS + h * HEAD_DIM;
        #pragma unroll
        for (int mt = 0; mt < 2; mt++) {
            const int rA = 32 * w + 16 * mt + g;
            #pragma unroll
            for (int kb = 0; kb < 3; kb++) {
                const int c = 16 * kb + 2 * t;
                #pragma unroll
                for (int e = 0; e < 4; e++) {
                    const int rr = rA + ((e & 1) ? 8 : 0);
                    const int cc = c + ((e & 2) ? 8 : 0);
                    uint32_t v = *reinterpret_cast<const uint32_t*>(gQ + (size_t)rr * QKV_COLS + cc);
                    __half2 hv = __hmul2(*reinterpret_cast<__half2*>(&v), qs2);
                    qh[mt][kb][e] = *reinterpret_cast<uint32_t*>(&hv);
                }
            }
        }
    }

    // query coords as half2 splats (4 rows: rr -> row 32w + 8rr + g)
    __half2 qcx2[4], qcy2[4], qcz2[4];
    #pragma unroll
    for (int rr = 0; rr < 4; rr++) {
        const int row = 32 * w + 8 * rr + g;
        const float* cp = coords + (size_t)(b * NTOK + q0 + row) * 3;
        qcx2[rr] = __float2half2_rn(__ldg(cp + 0));
        qcy2[rr] = __float2half2_rn(__ldg(cp + 1));
        qcz2[rr] = __float2half2_rn(__ldg(cp + 2));
    }

    float o[2][6][4];
    #pragma unroll
    for (int mt = 0; mt < 2; mt++)
        #pragma unroll
        for (int nb = 0; nb < 6; nb++)
            #pragma unroll
            for (int e = 0; e < 4; e++) o[mt][nb][e] = 0.f;

    float lsum[4] = {0.f, 0.f, 0.f, 0.f};

    for (int it = 0; it < N_ITERS; ++it) {
        __syncthreads();

        // ---- STS prefetched tile ----
        #pragma unroll
        for (int ii = 0; ii < 6; ii++) {
            const int i = tid + 256 * ii;
            const int r = i / 24, cu = i % 24;
            sKh[r * KSTR + cu] = pK[ii];
        }
        #pragma unroll
        for (int ii = 0; ii < 3; ii++) {
            const int p = tid + 256 * ii;
            const int kp = p / 24, dp = p % 24;
            const int d = 2 * dp;
            sVh[d * VSTR + kp]       = __byte_perm(pV[2 * ii], pV[2 * ii + 1], 0x5410);
            sVh[(d + 1) * VSTR + kp] = __byte_perm(pV[2 * ii], pV[2 * ii + 1], 0x7632);
        }
        if (tid < 96) sC2[ccomp][ckp] = __floats2half2_rn(pCa, pCb);
        __syncthreads();

        // ---- prefetch next tile ----
        if (it + 1 < N_ITERS) {
            const int j1 = (it + 1) * TJ;
            #pragma unroll
            for (int ii = 0; ii < 6; ii++) {
                const int i = tid + 256 * ii;
                const int r = i / 24, cu = i % 24;
                pK[ii] = *reinterpret_cast<const uint32_t*>(gKh + (size_t)(j1 + r) * QKV_COLS + 2 * cu);
            }
            #pragma unroll
            for (int ii = 0; ii < 3; ii++) {
                const int p = tid + 256 * ii;
                const int kp = p / 24, dp = p % 24;
                pV[2 * ii]     = *reinterpret_cast<const uint32_t*>(gVh + (size_t)(j1 + 2 * kp) * QKV_COLS + 2 * dp);
                pV[2 * ii + 1] = *reinterpret_cast<const uint32_t*>(gVh + (size_t)(j1 + 2 * kp + 1) * QKV_COLS + 2 * dp);
            }
            if (tid < 96) {
                pCa = __ldg(coords + (size_t)(b * NTOK + j1 + 2 * ckp) * 3 + ccomp);
                pCb = __ldg(coords + (size_t)(b * NTOK + j1 + 2 * ckp + 1) * 3 + ccomp);
            }
        }

        // ---- S = q @ k^T (single fp16) ----
        float s[2][8][4];
        #pragma unroll
        for (int mt = 0; mt < 2; mt++)
            #pragma unroll
            for (int nb = 0; nb < 8; nb++)
                #pragma unroll
                for (int e = 0; e < 4; e++) s[mt][nb][e] = 0.f;

        #pragma unroll
        for (int kb = 0; kb < 3; kb++) {
            #pragma unroll
            for (int nbp = 0; nbp < 4; nbp++) {
                const int nb0 = 2 * nbp, nb1 = 2 * nbp + 1;
                const int kb0 = (8 * nb0 + g) * KSTR + 8 * kb;
                const int kb1 = (8 * nb1 + g) * KSTR + 8 * kb;
                uint32_t b0h[2], b1h[2];
                b0h[0] = sKh[kb0 + t]; b0h[1] = sKh[kb0 + t + 4];
                b1h[0] = sKh[kb1 + t]; b1h[1] = sKh[kb1 + t + 4];
                mma_f16(s[0][nb0], qh[0][kb], b0h);
                mma_f16(s[0][nb1], qh[0][kb], b1h);
                mma_f16(s[1][nb0], qh[1][kb], b0h);
                mma_f16(s[1][nb1], qh[1][kb], b1h);
            }
        }

        // ---- per key-chunk: half2 softmax -> direct fp16 frags -> PV ----
        #pragma unroll
        for (int kb = 0; kb < 4; kb++) {
            uint32_t ah[2][4];
            #pragma unroll
            for (int nbo = 0; nbo < 2; nbo++) {
                const int nb = 2 * kb + nbo;
                const int kp = 4 * nb + t;
                const __half2 kx2 = sC2[0][kp], ky2 = sC2[1][kp], kz2 = sC2[2][kp];
                #pragma unroll
                for (int mt = 0; mt < 2; mt++) {
                    #pragma unroll
                    for (int hf = 0; hf < 2; hf++) {
                        const int rr = 2 * mt + hf;
                        __half2 dx = __hsub2(qcx2[rr], kx2);
                        __half2 dy = __hsub2(qcy2[rr], ky2);
                        __half2 dz = __hsub2(qcz2[rr], kz2);
                        __half2 d2 = __hfma2(dz, dz, __hfma2(dy, dy, __hmul2(dx, dx)));
                        float2 d2f = __half22float2(d2);
                        float l0 = fmaf(wd2, sqrt_approx(d2f.x), s[mt][nb][2 * hf]);
                        float l1 = fmaf(wd2, sqrt_approx(d2f.y), s[mt][nb][2 * hf + 1]);
                        uint32_t pfrag = ex2_h2(pack_f16(l0, l1));
                        ah[mt][2 * nbo + hf] = pfrag;
                        float2 pf = __half22float2(*reinterpret_cast<__half2*>(&pfrag));
                        lsum[rr] += pf.x + pf.y;
                    }
                }
            }
            // O += p @ v
            #pragma unroll
            for (int nbp = 0; nbp < 3; nbp++) {
                const int nb0 = 2 * nbp, nb1 = 2 * nbp + 1;
                const int vb0 = (8 * nb0 + g) * VSTR + 8 * kb;
                const int vb1 = (8 * nb1 + g) * VSTR + 8 * kb;
                uint32_t v0h[2], v1h[2];
                v0h[0] = sVh[vb0 + t]; v0h[1] = sVh[vb0 + t + 4];
                v1h[0] = sVh[vb1 + t]; v1h[1] = sVh[vb1 + t + 4];
                mma_f16(o[0][nb0], ah[0], v0h);
                mma_f16(o[0][nb1], ah[0], v1h);
                mma_f16(o[1][nb0], ah[1], v0h);
                mma_f16(o[1][nb1], ah[1], v1h);
            }
        }
    }

    // ---- finalize: reduce row sums, write hi/lo split halves ----
    #pragma unroll
    for (int rr = 0; rr < 4; rr++) {
        lsum[rr] += __shfl_xor_sync(0xffffffffu, lsum[rr], 1);
        lsum[rr] += __shfl_xor_sync(0xffffffffu, lsum[rr], 2);
        lsum[rr] = 1.f / lsum[rr];
    }

    #pragma unroll
    for (int mt = 0; mt < 2; mt++) {
        const int rowA = 32 * w + 16 * mt + g;
        const size_t baseA = (size_t)(b * NTOK + q0 + rowA) * D_MODEL + h * HEAD_DIM;
        const size_t baseB = baseA + (size_t)8 * D_MODEL;
        const float invA = lsum[2 * mt], invB = lsum[2 * mt + 1];
        #pragma unroll
        for (int nb = 0; nb < 6; nb++) {
            const int c = 8 * nb + 2 * t;
            uint32_t hiA, loA, hiB, loB;
            split_pair_f16(o[mt][nb][0] * invA, o[mt][nb][1] * invA, hiA, loA);
            split_pair_f16(o[mt][nb][2] * invB, o[mt][nb][3] * invB, hiB, loB);
            *reinterpret_cast<uint32_t*>(oh + baseA + c) = hiA;
            *reinterpret_cast<uint32_t*>(ol + baseA + c) = loA;
            *reinterpret_cast<uint32_t*>(oh + baseB + c) = hiB;
            *reinterpret_cast<uint32_t*>(ol + baseB + c) = loB;
        }
    }
}

// ---------------------------------------------------------------------------
extern "C" void kernel_launch(void* const* d_in, const int* in_sizes, int n_in,
                              void* d_out, int out_size)
{
    const float* x      = (const float*)d_in[0];
    const float* coords = (const float*)d_in[1];
    const float* W_qkv  = (const float*)d_in[2];
    const float* b_qkv  = (const float*)d_in[3];
    const float* W_dist = (const float*)d_in[4];
    const float* W_out  = (const float*)d_in[6];
    const float* b_out  = (const float*)d_in[7];
    float* out = (float*)d_out;

    __half *xh, *xl, *qkvh, *oh, *ol;
    uint32_t *wqt, *wot;
    cudaGetSymbolAddress((void**)&xh, g_xh);
    cudaGetSymbolAddress((void**)&xl, g_xl);
    cudaGetSymbolAddress((void**)&wqt, g_wqt);
    cudaGetSymbolAddress((void**)&wot, g_wot);
    cudaGetSymbolAddress((void**)&qkvh, g_qkvh);
    cudaGetSymbolAddress((void**)&oh, g_oh);
    cudaGetSymbolAddress((void**)&ol, g_ol);

    // 0) conversions
    split_x_kernel<<<(TOTAL_TOK * D_MODEL / 2 + 255) / 256, 256>>>(x, xh, xl, TOTAL_TOK * D_MODEL / 2);
    wtrans_kernel<<<(QKV_COLS * (D_MODEL / 2) + 255) / 256, 256>>>(W_qkv, wqt, QKV_COLS, D_MODEL);
    wtrans_kernel<<<(D_MODEL * (D_MODEL / 2) + 255) / 256, 256>>>(W_out, wot, D_MODEL, D_MODEL);

    // 1) QKV projection -> fp16 output
    {
        dim3 grid(QKV_COLS / GBN, TOTAL_TOK / GBM);
        gemm_h_kernel<__half><<<grid, 256>>>(xh, xl, wqt, b_qkv, qkvh,
                                             TOTAL_TOK, QKV_COLS, D_MODEL);
    }

    // 2) fused attention -> split fp16 output
    {
        dim3 grid(NTOK / MQ, BATCH * N_HEADS);
        attn_mma_kernel<<<grid, 256>>>(qkvh, coords, W_dist, oh, ol);
    }

    // 3) Output projection -> fp32
    {
        dim3 grid(D_MODEL / GBN, TOTAL_TOK / GBM);
        gemm_h_kernel<float><<<grid, 256>>>(oh, ol, wot, b_out, out,
                                            TOTAL_TOK, D_MODEL, D_MODEL);
    }
}

// round 13
// speedup vs baseline: 1.0639x; 1.0639x over previous
#include <cuda_runtime.h>
#include <cuda_bf16.h>
#include <cuda_fp16.h>
#include <cstdint>
#include <math.h>

#define D_MODEL 384
#define N_HEADS 8
#define HEAD_DIM 48
#define BATCH 2
#define NTOK 2048
#define TOTAL_TOK (BATCH * NTOK)
#define QKV_COLS (3 * D_MODEL)

// Scratch (allocation-free)
__device__ __half   g_xh[TOTAL_TOK * D_MODEL];
__device__ __half   g_xl[TOTAL_TOK * D_MODEL];
__device__ uint32_t g_wqt[QKV_COLS * (D_MODEL / 2)];   // [n][kp] half2
__device__ uint32_t g_wot[D_MODEL * (D_MODEL / 2)];
__device__ __half   g_qkvh[TOTAL_TOK * QKV_COLS];
__device__ __half   g_oh[TOTAL_TOK * D_MODEL];
__device__ __half   g_ol[TOTAL_TOK * D_MODEL];

// ---------------------------------------------------------------------------
// helpers
// ---------------------------------------------------------------------------
__device__ __forceinline__ void mma_f16(float* d, const uint32_t* a, const uint32_t* b) {
    asm volatile(
        "mma.sync.aligned.m16n8k16.row.col.f32.f16.f16.f32 "
        "{%0,%1,%2,%3}, {%4,%5,%6,%7}, {%8,%9}, {%0,%1,%2,%3};"
        : "+f"(d[0]), "+f"(d[1]), "+f"(d[2]), "+f"(d[3])
        : "r"(a[0]), "r"(a[1]), "r"(a[2]), "r"(a[3]), "r"(b[0]), "r"(b[1]));
}

__device__ __forceinline__ uint32_t pack_f16(float x, float y) {
    uint32_t r; asm("cvt.rn.f16x2.f32 %0, %1, %2;" : "=r"(r) : "f"(y), "f"(x)); return r;
}
__device__ __forceinline__ void split_pair_f16(float v0, float v1, uint32_t& hi, uint32_t& lo) {
    hi = pack_f16(v0, v1);
    __half2 h2 = *reinterpret_cast<__half2*>(&hi);
    float2 back = __half22float2(h2);
    lo = pack_f16(v0 - back.x, v1 - back.y);
}

__device__ __forceinline__ float sqrt_approx(float x) {
    float r; asm("sqrt.approx.f32 %0, %1;" : "=f"(r) : "f"(x)); return r;
}
__device__ __forceinline__ uint32_t ex2_h2(uint32_t x) {
    uint32_t r; asm("ex2.approx.f16x2 %0, %1;" : "=r"(r) : "r"(x)); return r;
}
__device__ __forceinline__ uint32_t smem_u32p(const void* p) {
    uint32_t a;
    asm("{ .reg .u64 t; cvta.to.shared.u64 t, %1; cvt.u32.u64 %0, t; }" : "=r"(a) : "l"(p));
    return a;
}
#define CP_ASYNC16(dst, src) \
    asm volatile("cp.async.cg.shared.global [%0], [%1], 16;" :: "r"(dst), "l"(src) : "memory")
#define CP_COMMIT() asm volatile("cp.async.commit_group;" ::: "memory")
#define CP_WAIT(n)  asm volatile("cp.async.wait_group %0;" :: "n"(n) : "memory")

// ---------------------------------------------------------------------------
// conversion kernels (once per launch)
// ---------------------------------------------------------------------------
__global__ __launch_bounds__(256)
void split_x_kernel(const float* __restrict__ x, __half* __restrict__ xh,
                    __half* __restrict__ xl, int n2)
{
    int i = blockIdx.x * 256 + threadIdx.x;
    if (i >= n2) return;
    float2 v = *reinterpret_cast<const float2*>(x + 2 * (size_t)i);
    uint32_t hi, lo;
    split_pair_f16(v.x, v.y, hi, lo);
    *reinterpret_cast<uint32_t*>(xh + 2 * (size_t)i) = hi;
    *reinterpret_cast<uint32_t*>(xl + 2 * (size_t)i) = lo;
}

__global__ __launch_bounds__(256)
void wtrans_kernel(const float* __restrict__ W, uint32_t* __restrict__ Wt, int N, int K)
{
    int idx = blockIdx.x * 256 + threadIdx.x;
    if (idx >= N * (K / 2)) return;
    int n = idx % N;
    int kp = idx / N;
    float b0 = __ldg(W + (size_t)(2 * kp) * N + n);
    float b1 = __ldg(W + (size_t)(2 * kp + 1) * N + n);
    Wt[(size_t)n * (K / 2) + kp] = pack_f16(b0, b1);
}

// ---------------------------------------------------------------------------
// 2-term FP16 GEMM, cp.async double-buffered k-loop.
// C = (Ah + Al) @ Bt + bias. BM=128, BN=64, BK=32; 256 threads.
// ---------------------------------------------------------------------------
#define GBM 128
#define GBN 64
#define GBK 32
#define ASTR 20
#define BSTR 20
#define A_TILE_U32 (GBM * ASTR)     // 2560
#define B_TILE_U32 (GBN * BSTR)     // 1280
#define SMEM_GEMM ((2 * A_TILE_U32 * 2 + 2 * B_TILE_U32) * 4)   // 51200 B

template <typename OutT>
__global__ __launch_bounds__(256)
void gemm_h_kernel(const __half* __restrict__ Ah, const __half* __restrict__ Al,
                   const uint32_t* __restrict__ Bt, const float* __restrict__ bias,
                   OutT* __restrict__ C, int M, int N, int K)
{
    extern __shared__ uint32_t smem[];
    uint32_t* sAh = smem;                        // [2][A_TILE_U32]
    uint32_t* sAl = smem + 2 * A_TILE_U32;       // [2][A_TILE_U32]
    uint32_t* sBh = smem + 4 * A_TILE_U32;       // [2][B_TILE_U32]

    const int tid = threadIdx.x;
    const int w = tid >> 5;
    const int lane = tid & 31;
    const int g = lane >> 2;
    const int t = lane & 3;
    const int wm = w >> 1;
    const int wn = w & 1;
    const int row0 = blockIdx.y * GBM;
    const int col0 = blockIdx.x * GBN;
    const int Kp = K / 2;
    const int NT = K / GBK;

    // copy maps (fixed per thread)
    const int a_r0 = (tid + 0)   >> 2, a_q0 = (tid + 0)   & 3;
    const int a_r1 = (tid + 256) >> 2, a_q1 = (tid + 256) & 3;
    const int b_n = tid >> 2, b_q = tid & 3;

    auto stage = [&](int k0, int buf) {
        uint32_t d;
        d = smem_u32p(&sAh[buf * A_TILE_U32 + a_r0 * ASTR + 4 * a_q0]);
        CP_ASYNC16(d, Ah + (size_t)(row0 + a_r0) * K + k0 + 8 * a_q0);
        d = smem_u32p(&sAl[buf * A_TILE_U32 + a_r0 * ASTR + 4 * a_q0]);
        CP_ASYNC16(d, Al + (size_t)(row0 + a_r0) * K + k0 + 8 * a_q0);
        d = smem_u32p(&sAh[buf * A_TILE_U32 + a_r1 * ASTR + 4 * a_q1]);
        CP_ASYNC16(d, Ah + (size_t)(row0 + a_r1) * K + k0 + 8 * a_q1);
        d = smem_u32p(&sAl[buf * A_TILE_U32 + a_r1 * ASTR + 4 * a_q1]);
        CP_ASYNC16(d, Al + (size_t)(row0 + a_r1) * K + k0 + 8 * a_q1);
        d = smem_u32p(&sBh[buf * B_TILE_U32 + b_n * BSTR + 4 * b_q]);
        CP_ASYNC16(d, Bt + (size_t)(col0 + b_n) * Kp + (k0 >> 1) + 4 * b_q);
        CP_COMMIT();
    };

    float acc[2][4][4];
    #pragma unroll
    for (int mt = 0; mt < 2; mt++)
        #pragma unroll
        for (int nb = 0; nb < 4; nb++)
            #pragma unroll
            for (int e = 0; e < 4; e++) acc[mt][nb][e] = 0.f;

    stage(0, 0);

    for (int kt = 0; kt < NT; kt++) {
        const int buf = kt & 1;
        if (kt + 1 < NT) {
            stage((kt + 1) * GBK, (kt + 1) & 1);
            CP_WAIT(1);
        } else {
            CP_WAIT(0);
        }
        __syncthreads();

        const uint32_t* cAh = sAh + buf * A_TILE_U32;
        const uint32_t* cAl = sAl + buf * A_TILE_U32;
        const uint32_t* cBh = sBh + buf * B_TILE_U32;

        #pragma unroll
        for (int kc = 0; kc < 2; kc++) {
            uint32_t ah[2][4], al[2][4];
            #pragma unroll
            for (int mt = 0; mt < 2; mt++) {
                const int rA = (32 * wm + 16 * mt + g) * ASTR + 8 * kc;
                const int rB = rA + 8 * ASTR;
                ah[mt][0] = cAh[rA + t];     al[mt][0] = cAl[rA + t];
                ah[mt][1] = cAh[rB + t];     al[mt][1] = cAl[rB + t];
                ah[mt][2] = cAh[rA + t + 4]; al[mt][2] = cAl[rA + t + 4];
                ah[mt][3] = cAh[rB + t + 4]; al[mt][3] = cAl[rB + t + 4];
            }
            #pragma unroll
            for (int nb = 0; nb < 4; nb++) {
                const int nbase = (32 * wn + 8 * nb + g) * BSTR + 8 * kc;
                uint32_t bh_[2];
                bh_[0] = cBh[nbase + t];
                bh_[1] = cBh[nbase + t + 4];
                mma_f16(acc[0][nb], ah[0], bh_);
                mma_f16(acc[1][nb], ah[1], bh_);
                mma_f16(acc[0][nb], al[0], bh_);
                mma_f16(acc[1][nb], al[1], bh_);
            }
        }
        __syncthreads();
    }

    #pragma unroll
    for (int mt = 0; mt < 2; mt++) {
        const int rA = row0 + 32 * wm + 16 * mt + g;
        #pragma unroll
        for (int nb = 0; nb < 4; nb++) {
            const int c = col0 + 32 * wn + 8 * nb + 2 * t;
            const float bx = bias[c], by = bias[c + 1];
            if constexpr (sizeof(OutT) == 4) {
                *reinterpret_cast<float2*>((float*)C + (size_t)rA * N + c) =
                    make_float2(acc[mt][nb][0] + bx, acc[mt][nb][1] + by);
                *reinterpret_cast<float2*>((float*)C + (size_t)(rA + 8) * N + c) =
                    make_float2(acc[mt][nb][2] + bx, acc[mt][nb][3] + by);
            } else {
                *reinterpret_cast<uint32_t*>((__half*)C + (size_t)rA * N + c) =
                    pack_f16(acc[mt][nb][0] + bx, acc[mt][nb][1] + by);
                *reinterpret_cast<uint32_t*>((__half*)C + (size_t)(rA + 8) * N + c) =
                    pack_f16(acc[mt][nb][2] + bx, acc[mt][nb][3] + by);
            }
        }
    }
}

// ---------------------------------------------------------------------------
// Fused attention (fp16 qkv, half2 softmax, ex2.f16x2 -> frags).
// V staging uses warp-tile map: conflict-free STS, 16B-contiguous LDG rows.
// ---------------------------------------------------------------------------
#define TJ 64
#define MQ 256
#define N_ITERS (NTOK / TJ)
#define KSTR 28
#define VSTR 36
#define LOG2E 1.4426950408889634f

__global__ __launch_bounds__(256, 1)
void attn_mma_kernel(const __half* __restrict__ qkv, const float* __restrict__ coords,
                     const float* __restrict__ W_dist,
                     __half* __restrict__ oh, __half* __restrict__ ol)
{
    __shared__ uint32_t sKh[TJ * KSTR];
    __shared__ uint32_t sVh[HEAD_DIM * VSTR];
    __shared__ __half2 sC2[3][TJ / 2];

    const int tid = threadIdx.x;
    const int w = tid >> 5;
    const int lane = tid & 31;
    const int g = lane >> 2;
    const int t = lane & 3;
    const int bh = blockIdx.y;
    const int b = bh >> 3, h = bh & 7;
    const int q0 = blockIdx.x * MQ;

    const float qscale = 0.14433756729740643f * LOG2E;
    const float wd2 = __ldg(W_dist + h) * LOG2E;
    const __half2 qs2 = __float2half2_rn(qscale);

    const __half* gKh = qkv + (size_t)(b * NTOK) * QKV_COLS + D_MODEL + h * HEAD_DIM;
    const __half* gVh = gKh + D_MODEL;

    uint32_t pK[6];
    uint32_t pV[6];
    float pCa = 0.f, pCb = 0.f;
    const int ccomp = tid % 3;      // valid for tid<96
    const int ckp = tid / 3;

    // V warp-tile map: wi = w + 8*ii; kp = 8*(wi&3) + (lane>>2); dp = 4*(wi>>2) + (lane&3)
    int v_kp[3], v_dp[3];
    #pragma unroll
    for (int ii = 0; ii < 3; ii++) {
        const int wi = w + 8 * ii;
        v_kp[ii] = 8 * (wi & 3) + (lane >> 2);
        v_dp[ii] = 4 * (wi >> 2) + (lane & 3);
    }

    // ---- initial prefetch (tile 0) ----
    #pragma unroll
    for (int ii = 0; ii < 6; ii++) {
        const int i = tid + 256 * ii;
        const int r = i / 24, cu = i % 24;
        pK[ii] = *reinterpret_cast<const uint32_t*>(gKh + (size_t)r * QKV_COLS + 2 * cu);
    }
    #pragma unroll
    for (int ii = 0; ii < 3; ii++) {
        pV[2 * ii]     = *reinterpret_cast<const uint32_t*>(gVh + (size_t)(2 * v_kp[ii]) * QKV_COLS + 2 * v_dp[ii]);
        pV[2 * ii + 1] = *reinterpret_cast<const uint32_t*>(gVh + (size_t)(2 * v_kp[ii] + 1) * QKV_COLS + 2 * v_dp[ii]);
    }
    if (tid < 96) {
        pCa = __ldg(coords + (size_t)(b * NTOK + 2 * ckp) * 3 + ccomp);
        pCb = __ldg(coords + (size_t)(b * NTOK + 2 * ckp + 1) * 3 + ccomp);
    }

    // ---- Q fragments: direct u32 loads, scaled in h2 ----
    uint32_t qh[2][3][4];
    {
        const __half* gQ = qkv + (size_t)(b * NTOK + q0) * QKV_COLS + h * HEAD_DIM;
        #pragma unroll
        for (int mt = 0; mt < 2; mt++) {
            const int rA = 32 * w + 16 * mt + g;
            #pragma unroll
            for (int kb = 0; kb < 3; kb++) {
                const int c = 16 * kb + 2 * t;
                #pragma unroll
                for (int e = 0; e < 4; e++) {
                    const int rr = rA + ((e & 1) ? 8 : 0);
                    const int cc = c + ((e & 2) ? 8 : 0);
                    uint32_t v = *reinterpret_cast<const uint32_t*>(gQ + (size_t)rr * QKV_COLS + cc);
                    __half2 hv = __hmul2(*reinterpret_cast<__half2*>(&v), qs2);
                    qh[mt][kb][e] = *reinterpret_cast<uint32_t*>(&hv);
                }
            }
        }
    }

    __half2 qcx2[4], qcy2[4], qcz2[4];
    #pragma unroll
    for (int rr = 0; rr < 4; rr++) {
        const int row = 32 * w + 8 * rr + g;
        const float* cp = coords + (size_t)(b * NTOK + q0 + row) * 3;
        qcx2[rr] = __float2half2_rn(__ldg(cp + 0));
        qcy2[rr] = __float2half2_rn(__ldg(cp + 1));
        qcz2[rr] = __float2half2_rn(__ldg(cp + 2));
    }

    float o[2][6][4];
    #pragma unroll
    for (int mt = 0; mt < 2; mt++)
        #pragma unroll
        for (int nb = 0; nb < 6; nb++)
            #pragma unroll
            for (int e = 0; e < 4; e++) o[mt][nb][e] = 0.f;

    float lsum[4] = {0.f, 0.f, 0.f, 0.f};

    for (int it = 0; it < N_ITERS; ++it) {
        __syncthreads();

        // ---- STS prefetched tile ----
        #pragma unroll
        for (int ii = 0; ii < 6; ii++) {
            const int i = tid + 256 * ii;
            const int r = i / 24, cu = i % 24;
            sKh[r * KSTR + cu] = pK[ii];
        }
        #pragma unroll
        for (int ii = 0; ii < 3; ii++) {
            const int d = 2 * v_dp[ii];
            const int kp = v_kp[ii];
            sVh[d * VSTR + kp]       = __byte_perm(pV[2 * ii], pV[2 * ii + 1], 0x5410);
            sVh[(d + 1) * VSTR + kp] = __byte_perm(pV[2 * ii], pV[2 * ii + 1], 0x7632);
        }
        if (tid < 96) sC2[ccomp][ckp] = __floats2half2_rn(pCa, pCb);
        __syncthreads();

        // ---- prefetch next tile ----
        if (it + 1 < N_ITERS) {
            const int j1 = (it + 1) * TJ;
            #pragma unroll
            for (int ii = 0; ii < 6; ii++) {
                const int i = tid + 256 * ii;
                const int r = i / 24, cu = i % 24;
                pK[ii] = *reinterpret_cast<const uint32_t*>(gKh + (size_t)(j1 + r) * QKV_COLS + 2 * cu);
            }
            #pragma unroll
            for (int ii = 0; ii < 3; ii++) {
                pV[2 * ii]     = *reinterpret_cast<const uint32_t*>(gVh + (size_t)(j1 + 2 * v_kp[ii]) * QKV_COLS + 2 * v_dp[ii]);
                pV[2 * ii + 1] = *reinterpret_cast<const uint32_t*>(gVh + (size_t)(j1 + 2 * v_kp[ii] + 1) * QKV_COLS + 2 * v_dp[ii]);
            }
            if (tid < 96) {
                pCa = __ldg(coords + (size_t)(b * NTOK + j1 + 2 * ckp) * 3 + ccomp);
                pCb = __ldg(coords + (size_t)(b * NTOK + j1 + 2 * ckp + 1) * 3 + ccomp);
            }
        }

        // ---- S = q @ k^T ----
        float s[2][8][4];
        #pragma unroll
        for (int mt = 0; mt < 2; mt++)
            #pragma unroll
            for (int nb = 0; nb < 8; nb++)
                #pragma unroll
                for (int e = 0; e < 4; e++) s[mt][nb][e] = 0.f;

        #pragma unroll
        for (int kb = 0; kb < 3; kb++) {
            #pragma unroll
            for (int nbp = 0; nbp < 4; nbp++) {
                const int nb0 = 2 * nbp, nb1 = 2 * nbp + 1;
                const int kb0 = (8 * nb0 + g) * KSTR + 8 * kb;
                const int kb1 = (8 * nb1 + g) * KSTR + 8 * kb;
                uint32_t b0h[2], b1h[2];
                b0h[0] = sKh[kb0 + t]; b0h[1] = sKh[kb0 + t + 4];
                b1h[0] = sKh[kb1 + t]; b1h[1] = sKh[kb1 + t + 4];
                mma_f16(s[0][nb0], qh[0][kb], b0h);
                mma_f16(s[0][nb1], qh[0][kb], b1h);
                mma_f16(s[1][nb0], qh[1][kb], b0h);
                mma_f16(s[1][nb1], qh[1][kb], b1h);
            }
        }

        // ---- per key-chunk: half2 softmax -> fp16 frags -> PV ----
        #pragma unroll
        for (int kb = 0; kb < 4; kb++) {
            uint32_t ah[2][4];
            #pragma unroll
            for (int nbo = 0; nbo < 2; nbo++) {
                const int nb = 2 * kb + nbo;
                const int kp = 4 * nb + t;
                const __half2 kx2 = sC2[0][kp], ky2 = sC2[1][kp], kz2 = sC2[2][kp];
                #pragma unroll
                for (int mt = 0; mt < 2; mt++) {
                    #pragma unroll
                    for (int hf = 0; hf < 2; hf++) {
                        const int rr = 2 * mt + hf;
                        __half2 dx = __hsub2(qcx2[rr], kx2);
                        __half2 dy = __hsub2(qcy2[rr], ky2);
                        __half2 dz = __hsub2(qcz2[rr], kz2);
                        __half2 d2 = __hfma2(dz, dz, __hfma2(dy, dy, __hmul2(dx, dx)));
                        float2 d2f = __half22float2(d2);
                        float l0 = fmaf(wd2, sqrt_approx(d2f.x), s[mt][nb][2 * hf]);
                        float l1 = fmaf(wd2, sqrt_approx(d2f.y), s[mt][nb][2 * hf + 1]);
                        uint32_t pfrag = ex2_h2(pack_f16(l0, l1));
                        ah[mt][2 * nbo + hf] = pfrag;
                        float2 pf = __half22float2(*reinterpret_cast<__half2*>(&pfrag));
                        lsum[rr] += pf.x + pf.y;
                    }
                }
            }
            #pragma unroll
            for (int nbp = 0; nbp < 3; nbp++) {
                const int nb0 = 2 * nbp, nb1 = 2 * nbp + 1;
                const int vb0 = (8 * nb0 + g) * VSTR + 8 * kb;
                const int vb1 = (8 * nb1 + g) * VSTR + 8 * kb;
                uint32_t v0h[2], v1h[2];
                v0h[0] = sVh[vb0 + t]; v0h[1] = sVh[vb0 + t + 4];
                v1h[0] = sVh[vb1 + t]; v1h[1] = sVh[vb1 + t + 4];
                mma_f16(o[0][nb0], ah[0], v0h);
                mma_f16(o[0][nb1], ah[0], v1h);
                mma_f16(o[1][nb0], ah[1], v0h);
                mma_f16(o[1][nb1], ah[1], v1h);
            }
        }
    }

    // ---- finalize ----
    #pragma unroll
    for (int rr = 0; rr < 4; rr++) {
        lsum[rr] += __shfl_xor_sync(0xffffffffu, lsum[rr], 1);
        lsum[rr] += __shfl_xor_sync(0xffffffffu, lsum[rr], 2);
        lsum[rr] = 1.f / lsum[rr];
    }

    #pragma unroll
    for (int mt = 0; mt < 2; mt++) {
        const int rowA = 32 * w + 16 * mt + g;
        const size_t baseA = (size_t)(b * NTOK + q0 + rowA) * D_MODEL + h * HEAD_DIM;
        const size_t baseB = baseA + (size_t)8 * D_MODEL;
        const float invA = lsum[2 * mt], invB = lsum[2 * mt + 1];
        #pragma unroll
        for (int nb = 0; nb < 6; nb++) {
            const int c = 8 * nb + 2 * t;
            uint32_t hiA, loA, hiB, loB;
            split_pair_f16(o[mt][nb][0] * invA, o[mt][nb][1] * invA, hiA, loA);
            split_pair_f16(o[mt][nb][2] * invB, o[mt][nb][3] * invB, hiB, loB);
            *reinterpret_cast<uint32_t*>(oh + baseA + c) = hiA;
            *reinterpret_cast<uint32_t*>(ol + baseA + c) = loA;
            *reinterpret_cast<uint32_t*>(oh + baseB + c) = hiB;
            *reinterpret_cast<uint32_t*>(ol + baseB + c) = loB;
        }
    }
}

// ---------------------------------------------------------------------------
extern "C" void kernel_launch(void* const* d_in, const int* in_sizes, int n_in,
                              void* d_out, int out_size)
{
    const float* x      = (const float*)d_in[0];
    const float* coords = (const float*)d_in[1];
    const float* W_qkv  = (const float*)d_in[2];
    const float* b_qkv  = (const float*)d_in[3];
    const float* W_dist = (const float*)d_in[4];
    const float* W_out  = (const float*)d_in[6];
    const float* b_out  = (const float*)d_in[7];
    float* out = (float*)d_out;

    __half *xh, *xl, *qkvh, *oh, *ol;
    uint32_t *wqt, *wot;
    cudaGetSymbolAddress((void**)&xh, g_xh);
    cudaGetSymbolAddress((void**)&xl, g_xl);
    cudaGetSymbolAddress((void**)&wqt, g_wqt);
    cudaGetSymbolAddress((void**)&wot, g_wot);
    cudaGetSymbolAddress((void**)&qkvh, g_qkvh);
    cudaGetSymbolAddress((void**)&oh, g_oh);
    cudaGetSymbolAddress((void**)&ol, g_ol);

    cudaFuncSetAttribute(gemm_h_kernel<__half>,
                         cudaFuncAttributeMaxDynamicSharedMemorySize, SMEM_GEMM);
    cudaFuncSetAttribute(gemm_h_kernel<float>,
                         cudaFuncAttributeMaxDynamicSharedMemorySize, SMEM_GEMM);

    // 0) conversions
    split_x_kernel<<<(TOTAL_TOK * D_MODEL / 2 + 255) / 256, 256>>>(x, xh, xl, TOTAL_TOK * D_MODEL / 2);
    wtrans_kernel<<<(QKV_COLS * (D_MODEL / 2) + 255) / 256, 256>>>(W_qkv, wqt, QKV_COLS, D_MODEL);
    wtrans_kernel<<<(D_MODEL * (D_MODEL / 2) + 255) / 256, 256>>>(W_out, wot, D_MODEL, D_MODEL);

    // 1) QKV projection -> fp16
    {
        dim3 grid(QKV_COLS / GBN, TOTAL_TOK / GBM);
        gemm_h_kernel<__half><<<grid, 256, SMEM_GEMM>>>(xh, xl, wqt, b_qkv, qkvh,
                                                        TOTAL_TOK, QKV_COLS, D_MODEL);
    }

    // 2) fused attention -> split fp16
    {
        dim3 grid(NTOK / MQ, BATCH * N_HEADS);
        attn_mma_kernel<<<grid, 256>>>(qkvh, coords, W_dist, oh, ol);
    }

    // 3) Output projection -> fp32
    {
        dim3 grid(D_MODEL / GBN, TOTAL_TOK / GBM);
        gemm_h_kernel<float><<<grid, 256, SMEM_GEMM>>>(oh, ol, wot, b_out, out,
                                                       TOTAL_TOK, D_MODEL, D_MODEL);
    }
}